// round 4
// baseline (speedup 1.0000x reference)
#include <cuda_runtime.h>
#include <cstdint>

#define B_    8
#define V_    100000
#define FIN_  32
#define K_    4
#define FOUT_ 64
#define E_    800000
#define TPV   256            // features per vertex = FIN_*B_
#define VF    (V_ * TPV)     // floats per Chebyshev order
#define SCAN_B ((V_ + 1023) / 1024)   // 98 scan blocks

// ---- scratch (static device globals; no allocation) ----
__device__ float d_x[3ull * VF];          // x0T, x1, x2 (x3 lives in shared of fused kernel)
__device__ int   d_counts[V_];            // zero at load; re-zeroed by scatter each run
__device__ int   d_rowptr[V_ + 1];
__device__ int   d_cursor[V_];
__device__ int   d_ccol[E_];
__device__ float d_cval[E_];
__device__ int   d_agg[SCAN_B];           // lookback flags: 0 = not ready, total+1 otherwise

// ---------------- packed f32x2 helpers (Blackwell) ----------------
__device__ __forceinline__ unsigned long long pack2(float a, float b) {
    unsigned long long r;
    asm("mov.b64 %0, {%1, %2};" : "=l"(r) : "f"(a), "f"(b));
    return r;
}
__device__ __forceinline__ unsigned long long fma2(unsigned long long x,
                                                   unsigned long long y,
                                                   unsigned long long c) {
    unsigned long long r;
    asm("fma.rn.f32x2 %0, %1, %2, %3;" : "=l"(r) : "l"(x), "l"(y), "l"(c));
    return r;
}
__device__ __forceinline__ void unpack2(unsigned long long v, float& lo, float& hi) {
    asm("mov.b64 {%0, %1}, %2;" : "=f"(lo), "=f"(hi) : "l"(v));
}

// ---------------- 1. CSR build ----------------
__global__ void hist_kernel(const int* __restrict__ rows) {
    int e = blockIdx.x * blockDim.x + threadIdx.x;
    if (e < E_) atomicAdd(&d_counts[rows[e]], 1);
}

__device__ __forceinline__ int block_exscan(int v, int* total) {
    const int lane = threadIdx.x & 31;
    const int wid = threadIdx.x >> 5;
    int inc = v;
    #pragma unroll
    for (int o = 1; o < 32; o <<= 1) {
        int n = __shfl_up_sync(0xffffffffu, inc, o);
        if (lane >= o) inc += n;
    }
    __shared__ int wsum[32];
    if (lane == 31) wsum[wid] = inc;
    __syncthreads();
    if (wid == 0) {
        int s = wsum[lane];
        #pragma unroll
        for (int o = 1; o < 32; o <<= 1) {
            int n = __shfl_up_sync(0xffffffffu, s, o);
            if (lane >= o) s += n;
        }
        wsum[lane] = s;
    }
    __syncthreads();
    int excl = inc - v + (wid ? wsum[wid - 1] : 0);
    *total = wsum[31];
    return excl;
}

// single-kernel scan with decoupled lookback (98 blocks, all co-resident)
__global__ __launch_bounds__(1024) void scan_kernel() {
    int i = blockIdx.x * 1024 + threadIdx.x;
    int c = (i < V_) ? d_counts[i] : 0;
    int total;
    int excl = block_exscan(c, &total);

    __shared__ int s_off;
    if (threadIdx.x == 0) {
        s_off = 0;
        __threadfence();
        atomicExch(&d_agg[blockIdx.x], total + 1);   // publish (payload in flag word)
    }
    __syncthreads();
    if ((int)threadIdx.x < (int)blockIdx.x) {
        int v;
        do { v = atomicAdd(&d_agg[threadIdx.x], 0); } while (v == 0);
        atomicAdd(&s_off, v - 1);
    }
    __syncthreads();
    const int off = s_off;
    if (i < V_) {
        int r = excl + off;
        d_rowptr[i] = r;
        d_cursor[i] = r;
    }
    if (i == 0) d_rowptr[V_] = E_;
}

// scatter + cleanup for next graph replay (counts & agg back to 0)
__global__ void scatter_kernel(const int* __restrict__ rows,
                               const int* __restrict__ cols,
                               const float* __restrict__ vals) {
    int e = blockIdx.x * blockDim.x + threadIdx.x;
    if (e < V_) d_counts[e] = 0;
    if (e < SCAN_B) d_agg[e] = 0;
    if (e >= E_) return;
    int r = rows[e];
    int p = atomicAdd(&d_cursor[r], 1);
    d_ccol[p] = cols[e];
    d_cval[p] = vals[e];
}

// ---------------- 2. SpMM pass 1 fused with transpose ----------------
// One warp per vertex, 8 vertices per 256-thread block.
// Lane l owns (b = l>>2, f = (l&3)*8 .. +7): gathers straight from inputs[b,v,f]
// (same 8x128B lines per edge as a transposed gather). Accumulates in b-major
// registers; converts to f-major [f*8+b] layout once per vertex via smem stage.
// Writes x1 = L x0 and x0T (transposed inputs).
__global__ __launch_bounds__(256) void spmm1_transpose_kernel(const float* __restrict__ in) {
    __shared__ float st[8][2 * TPV + 8];
    const int wrp = threadIdx.x >> 5;
    const int lane = threadIdx.x & 31;
    const int v = blockIdx.x * 8 + wrp;
    const int b = lane >> 2;
    const int f0 = (lane & 3) * 8;
    const float* base = in + (size_t)b * ((size_t)V_ * FIN_) + f0;  // + c*FIN_

    const int s = __ldg(&d_rowptr[v]);
    const int e = __ldg(&d_rowptr[v + 1]);

    float4 aA0 = make_float4(0.f, 0.f, 0.f, 0.f);  // edge-even, f0..f0+3
    float4 aA1 = make_float4(0.f, 0.f, 0.f, 0.f);  // edge-even, f0+4..f0+7
    float4 aB0 = make_float4(0.f, 0.f, 0.f, 0.f);
    float4 aB1 = make_float4(0.f, 0.f, 0.f, 0.f);
    int i = s;
    for (; i + 1 < e; i += 2) {
        int   c0 = __ldg(&d_ccol[i]);
        int   c1 = __ldg(&d_ccol[i + 1]);
        float w0 = __ldg(&d_cval[i]);
        float w1 = __ldg(&d_cval[i + 1]);
        float4 u0 = __ldg(reinterpret_cast<const float4*>(base + (size_t)c0 * FIN_));
        float4 u1 = __ldg(reinterpret_cast<const float4*>(base + (size_t)c0 * FIN_ + 4));
        float4 q0 = __ldg(reinterpret_cast<const float4*>(base + (size_t)c1 * FIN_));
        float4 q1 = __ldg(reinterpret_cast<const float4*>(base + (size_t)c1 * FIN_ + 4));
        aA0.x = fmaf(w0, u0.x, aA0.x); aA0.y = fmaf(w0, u0.y, aA0.y);
        aA0.z = fmaf(w0, u0.z, aA0.z); aA0.w = fmaf(w0, u0.w, aA0.w);
        aA1.x = fmaf(w0, u1.x, aA1.x); aA1.y = fmaf(w0, u1.y, aA1.y);
        aA1.z = fmaf(w0, u1.z, aA1.z); aA1.w = fmaf(w0, u1.w, aA1.w);
        aB0.x = fmaf(w1, q0.x, aB0.x); aB0.y = fmaf(w1, q0.y, aB0.y);
        aB0.z = fmaf(w1, q0.z, aB0.z); aB0.w = fmaf(w1, q0.w, aB0.w);
        aB1.x = fmaf(w1, q1.x, aB1.x); aB1.y = fmaf(w1, q1.y, aB1.y);
        aB1.z = fmaf(w1, q1.z, aB1.z); aB1.w = fmaf(w1, q1.w, aB1.w);
    }
    if (i < e) {
        int   c0 = __ldg(&d_ccol[i]);
        float w0 = __ldg(&d_cval[i]);
        float4 u0 = __ldg(reinterpret_cast<const float4*>(base + (size_t)c0 * FIN_));
        float4 u1 = __ldg(reinterpret_cast<const float4*>(base + (size_t)c0 * FIN_ + 4));
        aA0.x = fmaf(w0, u0.x, aA0.x); aA0.y = fmaf(w0, u0.y, aA0.y);
        aA0.z = fmaf(w0, u0.z, aA0.z); aA0.w = fmaf(w0, u0.w, aA0.w);
        aA1.x = fmaf(w0, u1.x, aA1.x); aA1.y = fmaf(w0, u1.y, aA1.y);
        aA1.z = fmaf(w0, u1.z, aA1.z); aA1.w = fmaf(w0, u1.w, aA1.w);
    }
    aA0.x += aB0.x; aA0.y += aB0.y; aA0.z += aB0.z; aA0.w += aB0.w;
    aA1.x += aB1.x; aA1.y += aB1.y; aA1.z += aB1.z; aA1.w += aB1.w;

    // own row (for transpose)
    float4 o0 = __ldg(reinterpret_cast<const float4*>(base + (size_t)v * FIN_));
    float4 o1 = __ldg(reinterpret_cast<const float4*>(base + (size_t)v * FIN_ + 4));

    // stage b-major -> f-major (j = f*8 + b)
    float* s1 = st[wrp];          // x1
    float* s0 = st[wrp] + TPV;    // x0T
    s1[(f0 + 0) * 8 + b] = aA0.x; s1[(f0 + 1) * 8 + b] = aA0.y;
    s1[(f0 + 2) * 8 + b] = aA0.z; s1[(f0 + 3) * 8 + b] = aA0.w;
    s1[(f0 + 4) * 8 + b] = aA1.x; s1[(f0 + 5) * 8 + b] = aA1.y;
    s1[(f0 + 6) * 8 + b] = aA1.z; s1[(f0 + 7) * 8 + b] = aA1.w;
    s0[(f0 + 0) * 8 + b] = o0.x;  s0[(f0 + 1) * 8 + b] = o0.y;
    s0[(f0 + 2) * 8 + b] = o0.z;  s0[(f0 + 3) * 8 + b] = o0.w;
    s0[(f0 + 4) * 8 + b] = o1.x;  s0[(f0 + 5) * 8 + b] = o1.y;
    s0[(f0 + 6) * 8 + b] = o1.z;  s0[(f0 + 7) * 8 + b] = o1.w;
    __syncwarp();

    float* x0T = d_x;
    float* x1g = d_x + (size_t)VF;
    *reinterpret_cast<float4*>(&x1g[(size_t)v * TPV + lane * 4]) =
        *reinterpret_cast<const float4*>(&s1[lane * 4]);
    *reinterpret_cast<float4*>(&x1g[(size_t)v * TPV + lane * 4 + 128]) =
        *reinterpret_cast<const float4*>(&s1[lane * 4 + 128]);
    *reinterpret_cast<float4*>(&x0T[(size_t)v * TPV + lane * 4]) =
        *reinterpret_cast<const float4*>(&s0[lane * 4]);
    *reinterpret_cast<float4*>(&x0T[(size_t)v * TPV + lane * 4 + 128]) =
        *reinterpret_cast<const float4*>(&s0[lane * 4 + 128]);
}

// ---------------- 3. SpMM pass 2: x2 = 2*(L x1) - x0 ----------------
__global__ __launch_bounds__(256) void spmm_kernel(const float* __restrict__ x,
                                                   const float* __restrict__ z,
                                                   float* __restrict__ y,
                                                   float alpha, float beta) {
    const int g = threadIdx.x >> 6;
    const int t = threadIdx.x & 63;
    const int v = blockIdx.x * 4 + g;
    const int s = __ldg(&d_rowptr[v]);
    const int e = __ldg(&d_rowptr[v + 1]);

    float4 a0 = make_float4(0.f, 0.f, 0.f, 0.f);
    float4 a1 = make_float4(0.f, 0.f, 0.f, 0.f);
    int i = s;
    for (; i + 1 < e; i += 2) {
        int   c0 = __ldg(&d_ccol[i]);
        int   c1 = __ldg(&d_ccol[i + 1]);
        float w0 = __ldg(&d_cval[i]);
        float w1 = __ldg(&d_cval[i + 1]);
        float4 x0 = __ldg(reinterpret_cast<const float4*>(&x[(size_t)c0 * TPV + t * 4]));
        float4 x1 = __ldg(reinterpret_cast<const float4*>(&x[(size_t)c1 * TPV + t * 4]));
        a0.x = fmaf(w0, x0.x, a0.x); a0.y = fmaf(w0, x0.y, a0.y);
        a0.z = fmaf(w0, x0.z, a0.z); a0.w = fmaf(w0, x0.w, a0.w);
        a1.x = fmaf(w1, x1.x, a1.x); a1.y = fmaf(w1, x1.y, a1.y);
        a1.z = fmaf(w1, x1.z, a1.z); a1.w = fmaf(w1, x1.w, a1.w);
    }
    if (i < e) {
        int   c0 = __ldg(&d_ccol[i]);
        float w0 = __ldg(&d_cval[i]);
        float4 x0 = __ldg(reinterpret_cast<const float4*>(&x[(size_t)c0 * TPV + t * 4]));
        a0.x = fmaf(w0, x0.x, a0.x); a0.y = fmaf(w0, x0.y, a0.y);
        a0.z = fmaf(w0, x0.z, a0.z); a0.w = fmaf(w0, x0.w, a0.w);
    }
    float4 r;
    r.x = alpha * (a0.x + a1.x);
    r.y = alpha * (a0.y + a1.y);
    r.z = alpha * (a0.z + a1.z);
    r.w = alpha * (a0.w + a1.w);
    if (beta != 0.f) {
        float4 zv = __ldg(reinterpret_cast<const float4*>(&z[(size_t)v * TPV + t * 4]));
        r.x = fmaf(beta, zv.x, r.x);
        r.y = fmaf(beta, zv.y, r.y);
        r.z = fmaf(beta, zv.z, r.z);
        r.w = fmaf(beta, zv.w, r.w);
    }
    *reinterpret_cast<float4*>(&y[(size_t)v * TPV + t * 4]) = r;
}

// ---------------- 4. FUSED: x3 = 2*L*x2 - x1 (into shared) + einsum + bias ----------------
__global__ __launch_bounds__(256) void spmm3_einsum_kernel(const float* __restrict__ w,
                                                           const float* __restrict__ bias,
                                                           float* __restrict__ out) {
    extern __shared__ float sm[];
    float* ws = sm;                      // 8192 floats
    float* xs = sm + FIN_ * K_ * FOUT_;  // 8 * 1024 floats, xs[v][k*256 + j]

    const int t = threadIdx.x;

    #pragma unroll
    for (int i = 0; i < FIN_ * K_ * FOUT_ / 256; i++) ws[i * 256 + t] = w[i * 256 + t];

    // ---- Phase A: SpMM for x3, one warp per vertex ----
    {
        const int sub = t >> 5;
        const int lane = t & 31;
        const int v = blockIdx.x * 8 + sub;
        const int p0 = lane * 4;
        const int p1 = lane * 4 + 128;
        const float* x2g = d_x + 2ull * VF;
        const float* x1g = d_x + 1ull * VF;
        const float* x0g = d_x;

        const int s = __ldg(&d_rowptr[v]);
        const int e = __ldg(&d_rowptr[v + 1]);
        float4 aA0 = make_float4(0.f, 0.f, 0.f, 0.f);
        float4 aA1 = make_float4(0.f, 0.f, 0.f, 0.f);
        float4 aB0 = make_float4(0.f, 0.f, 0.f, 0.f);
        float4 aB1 = make_float4(0.f, 0.f, 0.f, 0.f);
        int i = s;
        for (; i + 1 < e; i += 2) {
            int   c0 = __ldg(&d_ccol[i]);
            int   c1 = __ldg(&d_ccol[i + 1]);
            float w0 = __ldg(&d_cval[i]);
            float w1 = __ldg(&d_cval[i + 1]);
            float4 u0 = __ldg(reinterpret_cast<const float4*>(&x2g[(size_t)c0 * TPV + p0]));
            float4 u1 = __ldg(reinterpret_cast<const float4*>(&x2g[(size_t)c0 * TPV + p1]));
            float4 v0 = __ldg(reinterpret_cast<const float4*>(&x2g[(size_t)c1 * TPV + p0]));
            float4 v1 = __ldg(reinterpret_cast<const float4*>(&x2g[(size_t)c1 * TPV + p1]));
            aA0.x = fmaf(w0, u0.x, aA0.x); aA0.y = fmaf(w0, u0.y, aA0.y);
            aA0.z = fmaf(w0, u0.z, aA0.z); aA0.w = fmaf(w0, u0.w, aA0.w);
            aA1.x = fmaf(w0, u1.x, aA1.x); aA1.y = fmaf(w0, u1.y, aA1.y);
            aA1.z = fmaf(w0, u1.z, aA1.z); aA1.w = fmaf(w0, u1.w, aA1.w);
            aB0.x = fmaf(w1, v0.x, aB0.x); aB0.y = fmaf(w1, v0.y, aB0.y);
            aB0.z = fmaf(w1, v0.z, aB0.z); aB0.w = fmaf(w1, v0.w, aB0.w);
            aB1.x = fmaf(w1, v1.x, aB1.x); aB1.y = fmaf(w1, v1.y, aB1.y);
            aB1.z = fmaf(w1, v1.z, aB1.z); aB1.w = fmaf(w1, v1.w, aB1.w);
        }
        if (i < e) {
            int   c0 = __ldg(&d_ccol[i]);
            float w0 = __ldg(&d_cval[i]);
            float4 u0 = __ldg(reinterpret_cast<const float4*>(&x2g[(size_t)c0 * TPV + p0]));
            float4 u1 = __ldg(reinterpret_cast<const float4*>(&x2g[(size_t)c0 * TPV + p1]));
            aA0.x = fmaf(w0, u0.x, aA0.x); aA0.y = fmaf(w0, u0.y, aA0.y);
            aA0.z = fmaf(w0, u0.z, aA0.z); aA0.w = fmaf(w0, u0.w, aA0.w);
            aA1.x = fmaf(w0, u1.x, aA1.x); aA1.y = fmaf(w0, u1.y, aA1.y);
            aA1.z = fmaf(w0, u1.z, aA1.z); aA1.w = fmaf(w0, u1.w, aA1.w);
        }
        float4 z0 = __ldg(reinterpret_cast<const float4*>(&x1g[(size_t)v * TPV + p0]));
        float4 z1 = __ldg(reinterpret_cast<const float4*>(&x1g[(size_t)v * TPV + p1]));
        float4 r0, r1;
        r0.x = 2.f * (aA0.x + aB0.x) - z0.x;
        r0.y = 2.f * (aA0.y + aB0.y) - z0.y;
        r0.z = 2.f * (aA0.z + aB0.z) - z0.z;
        r0.w = 2.f * (aA0.w + aB0.w) - z0.w;
        r1.x = 2.f * (aA1.x + aB1.x) - z1.x;
        r1.y = 2.f * (aA1.y + aB1.y) - z1.y;
        r1.z = 2.f * (aA1.z + aB1.z) - z1.z;
        r1.w = 2.f * (aA1.w + aB1.w) - z1.w;

        float* xv = xs + sub * (K_ * TPV);
        *reinterpret_cast<float4*>(&xv[0 * TPV + p0]) =
            __ldg(reinterpret_cast<const float4*>(&x0g[(size_t)v * TPV + p0]));
        *reinterpret_cast<float4*>(&xv[0 * TPV + p1]) =
            __ldg(reinterpret_cast<const float4*>(&x0g[(size_t)v * TPV + p1]));
        *reinterpret_cast<float4*>(&xv[1 * TPV + p0]) = z0;
        *reinterpret_cast<float4*>(&xv[1 * TPV + p1]) = z1;
        *reinterpret_cast<float4*>(&xv[2 * TPV + p0]) =
            __ldg(reinterpret_cast<const float4*>(&x2g[(size_t)v * TPV + p0]));
        *reinterpret_cast<float4*>(&xv[2 * TPV + p1]) =
            __ldg(reinterpret_cast<const float4*>(&x2g[(size_t)v * TPV + p1]));
        *reinterpret_cast<float4*>(&xv[3 * TPV + p0]) = r0;
        *reinterpret_cast<float4*>(&xv[3 * TPV + p1]) = r1;
    }
    __syncthreads();

    // ---- Phase B: einsum. 4 groups x 64 threads; each group: 2 vertices ----
    const int g = t >> 6;
    const int o = t & 63;
    const float bo = __ldg(&bias[o]);
    const float* xv0 = xs + (g * 2 + 0) * (K_ * TPV);
    const float* xv1 = xs + (g * 2 + 1) * (K_ * TPV);

    unsigned long long a0[4] = {0ull, 0ull, 0ull, 0ull};
    unsigned long long a1[4] = {0ull, 0ull, 0ull, 0ull};
    #pragma unroll
    for (int k = 0; k < K_; k++) {
        #pragma unroll 4
        for (int f = 0; f < FIN_; f++) {
            float wv = ws[f * (K_ * FOUT_) + k * FOUT_ + o];
            unsigned long long wp = pack2(wv, wv);
            const ulonglong2* q0 = reinterpret_cast<const ulonglong2*>(&xv0[k * TPV + f * 8]);
            const ulonglong2* q1 = reinterpret_cast<const ulonglong2*>(&xv1[k * TPV + f * 8]);
            ulonglong2 p00 = q0[0];
            ulonglong2 p01 = q0[1];
            ulonglong2 p10 = q1[0];
            ulonglong2 p11 = q1[1];
            a0[0] = fma2(p00.x, wp, a0[0]);
            a0[1] = fma2(p00.y, wp, a0[1]);
            a0[2] = fma2(p01.x, wp, a0[2]);
            a0[3] = fma2(p01.y, wp, a0[3]);
            a1[0] = fma2(p10.x, wp, a1[0]);
            a1[1] = fma2(p10.y, wp, a1[1]);
            a1[2] = fma2(p11.x, wp, a1[2]);
            a1[3] = fma2(p11.y, wp, a1[3]);
        }
    }

    const int v0 = blockIdx.x * 8 + g * 2;
    float rb[8];
    #pragma unroll
    for (int j = 0; j < 4; j++) unpack2(a0[j], rb[2 * j], rb[2 * j + 1]);
    #pragma unroll
    for (int b = 0; b < B_; b++)
        out[((size_t)b * V_ + v0) * FOUT_ + o] = rb[b] + bo;
    #pragma unroll
    for (int j = 0; j < 4; j++) unpack2(a1[j], rb[2 * j], rb[2 * j + 1]);
    #pragma unroll
    for (int b = 0; b < B_; b++)
        out[((size_t)b * V_ + v0 + 1) * FOUT_ + o] = rb[b] + bo;
}

// ---------------- launch ----------------
extern "C" void kernel_launch(void* const* d_in, const int* in_sizes, int n_in,
                              void* d_out, int out_size) {
    const float* inputs = (const float*)d_in[0];
    const int*   rows   = (const int*)d_in[1];
    const int*   cols   = (const int*)d_in[2];
    const float* vals   = (const float*)d_in[3];
    const float* weight = (const float*)d_in[4];
    const float* bias   = (const float*)d_in[5];
    float* out = (float*)d_out;

    float* xbase;
    cudaGetSymbolAddress((void**)&xbase, d_x);

    static bool attr_set = false;
    if (!attr_set) {
        cudaFuncSetAttribute(spmm3_einsum_kernel,
                             cudaFuncAttributeMaxDynamicSharedMemorySize, 65536);
        attr_set = true;
    }

    // CSR build (counts/agg are zero from load or from previous run's scatter)
    hist_kernel<<<(E_ + 255) / 256, 256>>>(rows);          // 1
    scan_kernel<<<SCAN_B, 1024>>>();                        // 2
    scatter_kernel<<<(E_ + 255) / 256, 256>>>(rows, cols, vals); // 3

    float* x0T = xbase;
    float* x1 = xbase + (size_t)VF;
    float* x2 = xbase + 2 * (size_t)VF;

    // pass 1 + transpose (4th launch -> ncu sample target)
    spmm1_transpose_kernel<<<V_ / 8, 256>>>(inputs);        // 4

    // pass 2: x2 = 2 L x1 - x0
    spmm_kernel<<<V_ / 4, 256>>>(x1, x0T, x2, 2.0f, -1.0f); // 5

    // fused: x3 (shared) + einsum + bias
    spmm3_einsum_kernel<<<V_ / 8, 256, 65536>>>(weight, bias, out); // 6
}

// round 6
// speedup vs baseline: 1.0083x; 1.0083x over previous
#include <cuda_runtime.h>
#include <cstdint>

#define B_    8
#define V_    100000
#define FIN_  32
#define K_    4
#define FOUT_ 64
#define E_    800000
#define FH    128                      // floats per vertex per half (Fin * 4 batches)
#define HVF   ((size_t)V_ * FH)        // floats per Chebyshev order per half
#define SCAN_B ((V_ + 1023) / 1024)

// ---- scratch (static device globals; no allocation) ----
__device__ float d_x[3ull * HVF];      // x0T, x1, x2 for current half (reused across halves)
__device__ int   d_counts[V_];         // zero at load; re-zeroed by scatter each run
__device__ int   d_rowptr[V_ + 1];
__device__ int   d_cursor[V_];
__device__ int   d_ccol[E_];
__device__ float d_cval[E_];
__device__ int   d_agg[SCAN_B];

// ---------------- packed f32x2 helpers (Blackwell) ----------------
__device__ __forceinline__ unsigned long long pack2(float a, float b) {
    unsigned long long r;
    asm("mov.b64 %0, {%1, %2};" : "=l"(r) : "f"(a), "f"(b));
    return r;
}
__device__ __forceinline__ unsigned long long fma2(unsigned long long x,
                                                   unsigned long long y,
                                                   unsigned long long c) {
    unsigned long long r;
    asm("fma.rn.f32x2 %0, %1, %2, %3;" : "=l"(r) : "l"(x), "l"(y), "l"(c));
    return r;
}
__device__ __forceinline__ void unpack2(unsigned long long v, float& lo, float& hi) {
    asm("mov.b64 {%0, %1}, %2;" : "=f"(lo), "=f"(hi) : "l"(v));
}

// ---------------- CSR build ----------------
__global__ void hist_kernel(const int* __restrict__ rows) {
    int e = blockIdx.x * blockDim.x + threadIdx.x;
    if (e < E_) atomicAdd(&d_counts[rows[e]], 1);
}

__device__ __forceinline__ int block_exscan(int v, int* total) {
    const int lane = threadIdx.x & 31;
    const int wid = threadIdx.x >> 5;
    int inc = v;
    #pragma unroll
    for (int o = 1; o < 32; o <<= 1) {
        int n = __shfl_up_sync(0xffffffffu, inc, o);
        if (lane >= o) inc += n;
    }
    __shared__ int wsum[32];
    if (lane == 31) wsum[wid] = inc;
    __syncthreads();
    if (wid == 0) {
        int s = wsum[lane];
        #pragma unroll
        for (int o = 1; o < 32; o <<= 1) {
            int n = __shfl_up_sync(0xffffffffu, s, o);
            if (lane >= o) s += n;
        }
        wsum[lane] = s;
    }
    __syncthreads();
    int excl = inc - v + (wid ? wsum[wid - 1] : 0);
    *total = wsum[31];
    return excl;
}

__global__ __launch_bounds__(1024) void scan_kernel() {
    int i = blockIdx.x * 1024 + threadIdx.x;
    int c = (i < V_) ? d_counts[i] : 0;
    int total;
    int excl = block_exscan(c, &total);

    __shared__ int s_off;
    if (threadIdx.x == 0) {
        s_off = 0;
        __threadfence();
        atomicExch(&d_agg[blockIdx.x], total + 1);
    }
    __syncthreads();
    if ((int)threadIdx.x < (int)blockIdx.x) {
        int v;
        do { v = atomicAdd(&d_agg[threadIdx.x], 0); } while (v == 0);
        atomicAdd(&s_off, v - 1);
    }
    __syncthreads();
    const int off = s_off;
    if (i < V_) {
        int r = excl + off;
        d_rowptr[i] = r;
        d_cursor[i] = r;
    }
    if (i == 0) d_rowptr[V_] = E_;
}

__global__ void scatter_kernel(const int* __restrict__ rows,
                               const int* __restrict__ cols,
                               const float* __restrict__ vals) {
    int e = blockIdx.x * blockDim.x + threadIdx.x;
    if (e < V_) d_counts[e] = 0;
    if (e < SCAN_B) d_agg[e] = 0;
    if (e >= E_) return;
    int r = rows[e];
    int p = atomicAdd(&d_cursor[r], 1);
    d_ccol[p] = cols[e];
    d_cval[p] = vals[e];
}

// ---------------- SpMM pass 1 + transpose (per batch-half) ----------------
// One warp per vertex, 8 vertices per block. Lane l owns (bl = l>>3, f = (l&7)*4..+3):
// one LDG.128 per edge covering 4 FULLY-utilized 128B lines (one per batch slice).
// Result re-laid to [f*4+bl] via stride-5 smem staging (conflict-free).
__global__ __launch_bounds__(256) void spmm1t_kernel(const float* __restrict__ in, int h) {
    __shared__ float st[8][336];            // per warp: s1 @0 (160), s0 @168 (160)
    const int wrp = threadIdx.x >> 5;
    const int lane = threadIdx.x & 31;
    const int v = blockIdx.x * 8 + wrp;
    const int bl = lane >> 3;
    const int f0 = (lane & 7) * 4;
    const float* base = in + ((size_t)(h * 4 + bl) * V_) * FIN_ + f0;

    const int s = __ldg(&d_rowptr[v]);
    const int e = __ldg(&d_rowptr[v + 1]);

    float4 aA = make_float4(0.f, 0.f, 0.f, 0.f);
    float4 aB = make_float4(0.f, 0.f, 0.f, 0.f);
    int i = s;
    for (; i + 1 < e; i += 2) {
        int   c0 = __ldg(&d_ccol[i]);
        int   c1 = __ldg(&d_ccol[i + 1]);
        float w0 = __ldg(&d_cval[i]);
        float w1 = __ldg(&d_cval[i + 1]);
        float4 u = __ldg(reinterpret_cast<const float4*>(base + (size_t)c0 * FIN_));
        float4 q = __ldg(reinterpret_cast<const float4*>(base + (size_t)c1 * FIN_));
        aA.x = fmaf(w0, u.x, aA.x); aA.y = fmaf(w0, u.y, aA.y);
        aA.z = fmaf(w0, u.z, aA.z); aA.w = fmaf(w0, u.w, aA.w);
        aB.x = fmaf(w1, q.x, aB.x); aB.y = fmaf(w1, q.y, aB.y);
        aB.z = fmaf(w1, q.z, aB.z); aB.w = fmaf(w1, q.w, aB.w);
    }
    if (i < e) {
        int   c0 = __ldg(&d_ccol[i]);
        float w0 = __ldg(&d_cval[i]);
        float4 u = __ldg(reinterpret_cast<const float4*>(base + (size_t)c0 * FIN_));
        aA.x = fmaf(w0, u.x, aA.x); aA.y = fmaf(w0, u.y, aA.y);
        aA.z = fmaf(w0, u.z, aA.z); aA.w = fmaf(w0, u.w, aA.w);
    }
    aA.x += aB.x; aA.y += aB.y; aA.z += aB.z; aA.w += aB.w;

    // own row (transposed x0)
    float4 o0 = __ldg(reinterpret_cast<const float4*>(base + (size_t)v * FIN_));

    // stage: logical idx j = f*4+bl stored at j + (j>>2) = f*5 + bl  (conflict-free)
    float* s1 = st[wrp];
    float* s0 = st[wrp] + 168;
    s1[(f0 + 0) * 5 + bl] = aA.x; s1[(f0 + 1) * 5 + bl] = aA.y;
    s1[(f0 + 2) * 5 + bl] = aA.z; s1[(f0 + 3) * 5 + bl] = aA.w;
    s0[(f0 + 0) * 5 + bl] = o0.x; s0[(f0 + 1) * 5 + bl] = o0.y;
    s0[(f0 + 2) * 5 + bl] = o0.z; s0[(f0 + 3) * 5 + bl] = o0.w;
    __syncwarp();

    // read back: logical j = lane*4+m lives at 5*lane+m
    float4 r1, r0;
    r1.x = s1[5 * lane + 0]; r1.y = s1[5 * lane + 1];
    r1.z = s1[5 * lane + 2]; r1.w = s1[5 * lane + 3];
    r0.x = s0[5 * lane + 0]; r0.y = s0[5 * lane + 1];
    r0.z = s0[5 * lane + 2]; r0.w = s0[5 * lane + 3];

    float* x0T = d_x;
    float* x1g = d_x + HVF;
    *reinterpret_cast<float4*>(&x1g[(size_t)v * FH + lane * 4]) = r1;
    *reinterpret_cast<float4*>(&x0T[(size_t)v * FH + lane * 4]) = r0;
}

// ---------------- SpMM pass 2 (per half): y = 2*(L x) - z ----------------
__global__ __launch_bounds__(256) void spmm2_kernel(const float* __restrict__ x,
                                                    const float* __restrict__ z,
                                                    float* __restrict__ y) {
    const int wrp = threadIdx.x >> 5;
    const int lane = threadIdx.x & 31;
    const int v = blockIdx.x * 8 + wrp;
    const int p = lane * 4;
    const int s = __ldg(&d_rowptr[v]);
    const int e = __ldg(&d_rowptr[v + 1]);

    float4 a0 = make_float4(0.f, 0.f, 0.f, 0.f);
    float4 a1 = make_float4(0.f, 0.f, 0.f, 0.f);
    int i = s;
    for (; i + 1 < e; i += 2) {
        int   c0 = __ldg(&d_ccol[i]);
        int   c1 = __ldg(&d_ccol[i + 1]);
        float w0 = __ldg(&d_cval[i]);
        float w1 = __ldg(&d_cval[i + 1]);
        float4 u = __ldg(reinterpret_cast<const float4*>(&x[(size_t)c0 * FH + p]));
        float4 q = __ldg(reinterpret_cast<const float4*>(&x[(size_t)c1 * FH + p]));
        a0.x = fmaf(w0, u.x, a0.x); a0.y = fmaf(w0, u.y, a0.y);
        a0.z = fmaf(w0, u.z, a0.z); a0.w = fmaf(w0, u.w, a0.w);
        a1.x = fmaf(w1, q.x, a1.x); a1.y = fmaf(w1, q.y, a1.y);
        a1.z = fmaf(w1, q.z, a1.z); a1.w = fmaf(w1, q.w, a1.w);
    }
    if (i < e) {
        int   c0 = __ldg(&d_ccol[i]);
        float w0 = __ldg(&d_cval[i]);
        float4 u = __ldg(reinterpret_cast<const float4*>(&x[(size_t)c0 * FH + p]));
        a0.x = fmaf(w0, u.x, a0.x); a0.y = fmaf(w0, u.y, a0.y);
        a0.z = fmaf(w0, u.z, a0.z); a0.w = fmaf(w0, u.w, a0.w);
    }
    float4 zv = __ldg(reinterpret_cast<const float4*>(&z[(size_t)v * FH + p]));
    float4 r;
    r.x = 2.f * (a0.x + a1.x) - zv.x;
    r.y = 2.f * (a0.y + a1.y) - zv.y;
    r.z = 2.f * (a0.z + a1.z) - zv.z;
    r.w = 2.f * (a0.w + a1.w) - zv.w;
    *reinterpret_cast<float4*>(&y[(size_t)v * FH + p]) = r;
}

// ---------------- FUSED (per half): x3 = 2*L*x2 - x1 in shared + einsum + bias --------
// 256 threads, 16 vertices/block. Phase A: each warp gathers for 2 vertices.
// Phase B: 4 groups x 64 threads (o-lane); each group does 4 vertices so every
// weight LDS feeds 8 fma2.
__global__ __launch_bounds__(256) void spmm3_einsum_kernel(const float* __restrict__ w,
                                                           const float* __restrict__ bias,
                                                           float* __restrict__ out, int h) {
    extern __shared__ float sm[];
    float* ws = sm;                       // 8192 floats
    float* xs = sm + FIN_ * K_ * FOUT_;   // 16 vertices * 512 floats: [vert][k*128 + f*4+bl]

    const int t = threadIdx.x;
    #pragma unroll
    for (int i = 0; i < FIN_ * K_ * FOUT_ / 256; i++) ws[i * 256 + t] = w[i * 256 + t];

    // ---- Phase A ----
    {
        const int wrp = t >> 5;
        const int lane = t & 31;
        const int p = lane * 4;
        const float* x0g = d_x;
        const float* x1g = d_x + HVF;
        const float* x2g = d_x + 2 * HVF;

        #pragma unroll
        for (int vv = 0; vv < 2; vv++) {
            const int vert = wrp * 2 + vv;
            const int v = blockIdx.x * 16 + vert;
            const int s = __ldg(&d_rowptr[v]);
            const int e = __ldg(&d_rowptr[v + 1]);
            float4 a0 = make_float4(0.f, 0.f, 0.f, 0.f);
            float4 a1 = make_float4(0.f, 0.f, 0.f, 0.f);
            int i = s;
            for (; i + 1 < e; i += 2) {
                int   c0 = __ldg(&d_ccol[i]);
                int   c1 = __ldg(&d_ccol[i + 1]);
                float w0 = __ldg(&d_cval[i]);
                float w1 = __ldg(&d_cval[i + 1]);
                float4 u = __ldg(reinterpret_cast<const float4*>(&x2g[(size_t)c0 * FH + p]));
                float4 q = __ldg(reinterpret_cast<const float4*>(&x2g[(size_t)c1 * FH + p]));
                a0.x = fmaf(w0, u.x, a0.x); a0.y = fmaf(w0, u.y, a0.y);
                a0.z = fmaf(w0, u.z, a0.z); a0.w = fmaf(w0, u.w, a0.w);
                a1.x = fmaf(w1, q.x, a1.x); a1.y = fmaf(w1, q.y, a1.y);
                a1.z = fmaf(w1, q.z, a1.z); a1.w = fmaf(w1, q.w, a1.w);
            }
            if (i < e) {
                int   c0 = __ldg(&d_ccol[i]);
                float w0 = __ldg(&d_cval[i]);
                float4 u = __ldg(reinterpret_cast<const float4*>(&x2g[(size_t)c0 * FH + p]));
                a0.x = fmaf(w0, u.x, a0.x); a0.y = fmaf(w0, u.y, a0.y);
                a0.z = fmaf(w0, u.z, a0.z); a0.w = fmaf(w0, u.w, a0.w);
            }
            float4 z1 = __ldg(reinterpret_cast<const float4*>(&x1g[(size_t)v * FH + p]));
            float4 r;
            r.x = 2.f * (a0.x + a1.x) - z1.x;
            r.y = 2.f * (a0.y + a1.y) - z1.y;
            r.z = 2.f * (a0.z + a1.z) - z1.z;
            r.w = 2.f * (a0.w + a1.w) - z1.w;

            float* xv = xs + vert * (K_ * FH);
            *reinterpret_cast<float4*>(&xv[0 * FH + p]) =
                __ldg(reinterpret_cast<const float4*>(&x0g[(size_t)v * FH + p]));
            *reinterpret_cast<float4*>(&xv[1 * FH + p]) = z1;
            *reinterpret_cast<float4*>(&xv[2 * FH + p]) =
                __ldg(reinterpret_cast<const float4*>(&x2g[(size_t)v * FH + p]));
            *reinterpret_cast<float4*>(&xv[3 * FH + p]) = r;
        }
    }
    __syncthreads();

    // ---- Phase B ----
    const int g = t >> 6;
    const int o = t & 63;
    const float bo = __ldg(&bias[o]);
    const float* xb = xs + g * 4 * (K_ * FH);

    unsigned long long a[4][2] = {{0ull,0ull},{0ull,0ull},{0ull,0ull},{0ull,0ull}};
    #pragma unroll 4
    for (int f = 0; f < FIN_; f++) {
        #pragma unroll
        for (int k = 0; k < K_; k++) {
            float wv = ws[f * (K_ * FOUT_) + k * FOUT_ + o];
            unsigned long long wp = pack2(wv, wv);
            #pragma unroll
            for (int j = 0; j < 4; j++) {
                ulonglong2 p = *reinterpret_cast<const ulonglong2*>(
                    &xb[j * (K_ * FH) + k * FH + f * 4]);
                a[j][0] = fma2(p.x, wp, a[j][0]);
                a[j][1] = fma2(p.y, wp, a[j][1]);
            }
        }
    }

    #pragma unroll
    for (int j = 0; j < 4; j++) {
        const int v = blockIdx.x * 16 + g * 4 + j;
        float b0, b1, b2, b3;
        unpack2(a[j][0], b0, b1);
        unpack2(a[j][1], b2, b3);
        out[((size_t)(h * 4 + 0) * V_ + v) * FOUT_ + o] = b0 + bo;
        out[((size_t)(h * 4 + 1) * V_ + v) * FOUT_ + o] = b1 + bo;
        out[((size_t)(h * 4 + 2) * V_ + v) * FOUT_ + o] = b2 + bo;
        out[((size_t)(h * 4 + 3) * V_ + v) * FOUT_ + o] = b3 + bo;
    }
}

// ---------------- launch ----------------
extern "C" void kernel_launch(void* const* d_in, const int* in_sizes, int n_in,
                              void* d_out, int out_size) {
    const float* inputs = (const float*)d_in[0];
    const int*   rows   = (const int*)d_in[1];
    const int*   cols   = (const int*)d_in[2];
    const float* vals   = (const float*)d_in[3];
    const float* weight = (const float*)d_in[4];
    const float* bias   = (const float*)d_in[5];
    float* out = (float*)d_out;

    float* xbase;
    cudaGetSymbolAddress((void**)&xbase, d_x);

    static bool attr_set = false;
    if (!attr_set) {
        cudaFuncSetAttribute(spmm3_einsum_kernel,
                             cudaFuncAttributeMaxDynamicSharedMemorySize, 65536);
        attr_set = true;
    }

    // CSR build
    hist_kernel<<<(E_ + 255) / 256, 256>>>(rows);                 // 1
    scan_kernel<<<SCAN_B, 1024>>>();                               // 2
    scatter_kernel<<<(E_ + 255) / 256, 256>>>(rows, cols, vals);   // 3

    float* x0T = xbase;
    float* x1 = xbase + HVF;
    float* x2 = xbase + 2 * HVF;

    for (int h = 0; h < 2; h++) {
        spmm1t_kernel<<<V_ / 8, 256>>>(inputs, h);                 // 4 (h=0): ncu target
        spmm2_kernel<<<V_ / 8, 256>>>(x1, x0T, x2);                // 5
        spmm3_einsum_kernel<<<V_ / 16, 256, 65536>>>(weight, bias, out, h); // 6
    }
}